// round 6
// baseline (speedup 1.0000x reference)
#include <cuda_runtime.h>
#include <cstdint>

// Problem constants
#define BB 8
#define LL 4096
#define DD 768
#define NB 592                 // 148 SMs x 4 blocks (co-resident, <= 152x4 on GB300)
#define NTHREADS 256

// Phase 1: 16-row chunks
#define NCH1 2048              // (BB*LL)/16
#define RPC1 16
#define CH_PER_B 256           // chunks per batch
// Phase 2: 24 units = 8 batches x 3 column groups of 256
#define NUNIT 24
// Phase 3: 8-row groups
#define NGRP 4096              // (BB*LL)/8
#define GRP_PER_B 512

// Scratch (device globals; zero-initialized once). No .cs hints (R2/R3 regressions).
__device__ __align__(16) float g_part[NCH1 * DD];     // 6 MB partial colsums
__device__ __align__(16) float g_sum[BB * DD];        // full column sums
__device__ float g_sqpart[BB * 3];                    // per-unit sum of squares
__device__ unsigned g_arrive = 0;                     // epoch barrier counter (monotone)
__device__ unsigned g_ticket1 = 0;                    // phase-1 work ticket
__device__ unsigned g_ticket2 = 0;                    // phase-3 work ticket

// Epoch-based grid barrier: monotone counter, no reset needed across launches.
__device__ __forceinline__ void grid_barrier() {
    __syncthreads();
    if (threadIdx.x == 0) {
        __threadfence();                       // publish this block's prior writes
        unsigned old = atomicAdd(&g_arrive, 1u);
        unsigned target = (old / NB + 1u) * NB;
        while ((int)(*(volatile unsigned*)&g_arrive - target) < 0)
            __nanosleep(32);
    }
    __syncthreads();
}

__global__ __launch_bounds__(NTHREADS, 4) void fused_kernel(const float* __restrict__ x,
                                                            const float* __restrict__ alpha,
                                                            float* __restrict__ out) {
    __shared__ float4 smean[DD / 4];   // 3 KB: sum_b row
    __shared__ unsigned s_claim;
    __shared__ int s_prevb;
    __shared__ float s_coef;
    const int tid = threadIdx.x;

    // ticket2 holds stale value from previous launch; reset before barrier 2.
    if (blockIdx.x == 0 && tid == 0) g_ticket2 = 0;

    // ---------------- Phase 1: partial column sums (ticketed 16-row chunks) --
    for (;;) {
        __syncthreads();
        if (tid == 0) s_claim = atomicAdd(&g_ticket1, 1u);
        __syncthreads();
        const unsigned c = s_claim;
        if (c >= NCH1) break;
        if (tid < DD / 4) {
            const float4* xp = reinterpret_cast<const float4*>(x) +
                               (size_t)c * RPC1 * (DD / 4) + tid;
            float4 s0 = make_float4(0.f, 0.f, 0.f, 0.f);
            float4 s1 = make_float4(0.f, 0.f, 0.f, 0.f);
            float4 s2 = make_float4(0.f, 0.f, 0.f, 0.f);
            float4 s3 = make_float4(0.f, 0.f, 0.f, 0.f);
#pragma unroll
            for (int i = 0; i < RPC1; i += 4) {
                float4 v0 = xp[(size_t)(i + 0) * (DD / 4)];
                float4 v1 = xp[(size_t)(i + 1) * (DD / 4)];
                float4 v2 = xp[(size_t)(i + 2) * (DD / 4)];
                float4 v3 = xp[(size_t)(i + 3) * (DD / 4)];
                s0.x += v0.x; s0.y += v0.y; s0.z += v0.z; s0.w += v0.w;
                s1.x += v1.x; s1.y += v1.y; s1.z += v1.z; s1.w += v1.w;
                s2.x += v2.x; s2.y += v2.y; s2.z += v2.z; s2.w += v2.w;
                s3.x += v3.x; s3.y += v3.y; s3.z += v3.z; s3.w += v3.w;
            }
            float4 s = make_float4((s0.x + s1.x) + (s2.x + s3.x),
                                   (s0.y + s1.y) + (s2.y + s3.y),
                                   (s0.z + s1.z) + (s2.z + s3.z),
                                   (s0.w + s1.w) + (s2.w + s3.w));
            reinterpret_cast<float4*>(g_part)[(size_t)c * (DD / 4) + tid] = s;
        }
    }

    grid_barrier();
    if (blockIdx.x == 0 && tid == 0) g_ticket1 = 0;   // for next launch

    // ---------------- Phase 2: finish colsums + square-sums (24 units) -------
    if (blockIdx.x < NUNIT) {
        const int b = blockIdx.x / 3;
        const int g = blockIdx.x % 3;
        const int col = g * 256 + tid;

        const float* p = g_part + (size_t)b * CH_PER_B * DD + col;
        float a0 = 0.f, a1 = 0.f, a2 = 0.f, a3 = 0.f;
#pragma unroll 4
        for (int c = 0; c < CH_PER_B; c += 4) {
            a0 += p[(size_t)(c + 0) * DD];
            a1 += p[(size_t)(c + 1) * DD];
            a2 += p[(size_t)(c + 2) * DD];
            a3 += p[(size_t)(c + 3) * DD];
        }
        const float s = (a0 + a1) + (a2 + a3);
        g_sum[b * DD + col] = s;

        __shared__ float red[NTHREADS];
        red[tid] = s * s;
        __syncthreads();
#pragma unroll
        for (int o = 128; o > 32; o >>= 1) {
            if (tid < o) red[tid] += red[tid + o];
            __syncthreads();
        }
        if (tid < 32) {
            float v = red[tid] + red[tid + 32];
#pragma unroll
            for (int off = 16; off > 0; off >>= 1)
                v += __shfl_xor_sync(0xFFFFFFFFu, v, off);
            if (tid == 0) g_sqpart[b * 3 + g] = v;
        }
    }

    grid_barrier();

    // ---------------- Phase 3: finalize (ticketed 8-row groups, REVERSE) -----
    // Reverse traversal vs phase 1: out-write L2 victims (LRU = earliest x rows)
    // ascend from row 0 while the reader descends -> ~half the x re-reads hit L2.
    if (tid == 0) s_prevb = -1;

    const float4* gsum4 = reinterpret_cast<const float4*>(g_sum);
    for (;;) {
        __syncthreads();
        if (tid == 0) s_claim = atomicAdd(&g_ticket2, 1u);
        __syncthreads();
        const unsigned cl = s_claim;
        if (cl >= NGRP) break;
        const int grp = (NGRP - 1) - (int)cl;      // descending rows
        const int b = grp >> 9;                    // 512 groups per batch

        if (b != s_prevb) {
            if (tid < DD / 4) smean[tid] = gsum4[b * (DD / 4) + tid];
            if (tid == 0) {
                const float sq = g_sqpart[b * 3 + 0] + g_sqpart[b * 3 + 1]
                               + g_sqpart[b * 3 + 2];
                const double denom = (double)DD * (double)DD
                                   * (double)LL * (double)LL * (double)LL * (double)LL;
                s_coef = (float)((double)sq / denom);
                s_prevb = b;
            }
            __syncthreads();
        }

        const int warp = tid >> 5;
        const int lane = tid & 31;
        const int row  = grp * 8 + warp;           // one row per warp
        const int l    = row & (LL - 1);

        const float4* xp = reinterpret_cast<const float4*>(x + (size_t)row * DD);
        float4 v[6];
        float dot = 0.f;
#pragma unroll
        for (int i = 0; i < 6; i++) {
            v[i] = xp[lane + i * 32];
            float4 m = smean[lane + i * 32];
            dot += v[i].x * m.x + v[i].y * m.y + v[i].z * m.z + v[i].w * m.w;
        }
#pragma unroll
        for (int off = 16; off > 0; off >>= 1)
            dot += __shfl_xor_sync(0xFFFFFFFFu, dot, off);

        const float y2 = dot * s_coef;
        const float a  = alpha[l];

        float4* op = reinterpret_cast<float4*>(out + (size_t)row * DD);
#pragma unroll
        for (int i = 0; i < 6; i++) {
            float4 o;
            o.x = a + y2 * v[i].x;
            o.y = a + y2 * v[i].y;
            o.z = a + y2 * v[i].z;
            o.w = a + y2 * v[i].w;
            op[lane + i * 32] = o;
        }
    }
}

extern "C" void kernel_launch(void* const* d_in, const int* in_sizes, int n_in,
                              void* d_out, int out_size) {
    const float* x     = (const float*)d_in[0];   // [8, 4096, 768] f32
    const float* alpha = (const float*)d_in[1];   // [4096, 1] f32
    float* out = (float*)d_out;                   // [8, 4096, 768] f32

    fused_kernel<<<NB, NTHREADS>>>(x, alpha, out);
}